// round 10
// baseline (speedup 1.0000x reference)
#include <cuda_runtime.h>
#include <cstdint>

#define POOL 7
#define NUM_ROIS 512
#define IMG_W 128
#define CH 1024
#define N_CELLS (NUM_ROIS * POOL * POOL)   // 25088
#define F4C 256                            // float4 per pixel vector (1024 ch)
#define NBINS (128 * 128)                  // pixel-index bins
#define CPB 16                             // sorted cells per block (25088/16 = 1568)

__device__ int      g_hist[NBINS];
__device__ int      g_binoff[NBINS];
__device__ int      g_perm[N_CELLS];
__device__ uint16_t g_key[N_CELLS];
__device__ int4     g_offs[N_CELLS];       // corner offsets in float4 units
__device__ float4   g_wts[N_CELLS];        // bilinear weights

// ---------------- K0: zero histogram ----------------
__global__ void zero_kernel() {
    const int i = blockIdx.x * 256 + threadIdx.x;
    if (i < NBINS) g_hist[i] = 0;
}

// ---------------- K1: per-cell params + key + histogram ----------------
__global__ void setup_kernel(const int* __restrict__ rois) {
    const int cell = blockIdx.x * 256 + threadIdx.x;
    if (cell >= N_CELLS) return;

    const int roi = cell / (POOL * POOL);
    const int rem = cell - roi * (POOL * POOL);
    const int py  = rem / POOL;
    const int px  = rem - py * POOL;

    const int x = rois[roi * 4 + 0];
    const int y = rois[roi * 4 + 1];
    const int w = rois[roi * 4 + 2];
    const int h = rois[roi * 4 + 3];

    const float hf = (float)h;
    const float wf = (float)w;

    // half-pixel-center source coords, clamped (matches tf.image.resize bilinear)
    float ys = ((float)py + 0.5f) * hf * (1.0f / POOL) - 0.5f;
    float xs = ((float)px + 0.5f) * wf * (1.0f / POOL) - 0.5f;
    ys = fminf(fmaxf(ys, 0.0f), hf - 1.0f);
    xs = fminf(fmaxf(xs, 0.0f), wf - 1.0f);

    const int y0 = (int)floorf(ys);
    const int x0 = (int)floorf(xs);
    const int y1 = min(y0 + 1, h - 1);
    const int x1 = min(x0 + 1, w - 1);
    const float fy = ys - (float)y0;
    const float fx = xs - (float)x0;

    const int ay0 = y + y0, ay1 = y + y1;
    const int ax0 = x + x0, ax1 = x + x1;

    int4 off;
    off.x = (ay0 * IMG_W + ax0) * F4C;
    off.y = (ay0 * IMG_W + ax1) * F4C;
    off.z = (ay1 * IMG_W + ax0) * F4C;
    off.w = (ay1 * IMG_W + ax1) * F4C;
    g_offs[cell] = off;

    float4 wt;
    wt.x = (1.0f - fy) * (1.0f - fx);
    wt.y = (1.0f - fy) * fx;
    wt.z = fy * (1.0f - fx);
    wt.w = fy * fx;
    g_wts[cell] = wt;

    const int key = ay0 * IMG_W + ax0;     // spatial sort key
    g_key[cell] = (uint16_t)key;
    atomicAdd(&g_hist[key], 1);
}

// ---------------- K2: exclusive scan of 16384 bins, one block ----------------
__global__ void scan_kernel() {
    __shared__ int part[256];
    const int t = threadIdx.x;
    const int base = t * 64;

    int sum = 0;
#pragma unroll
    for (int i = 0; i < 64; i++) sum += g_hist[base + i];
    part[t] = sum;
    __syncthreads();

    // Hillis-Steele inclusive scan over 256 partials
    for (int d = 1; d < 256; d <<= 1) {
        int v = (t >= d) ? part[t - d] : 0;
        __syncthreads();
        part[t] += v;
        __syncthreads();
    }

    int excl = part[t] - sum;               // exclusive prefix of this chunk
#pragma unroll
    for (int i = 0; i < 64; i++) {
        const int c = g_hist[base + i];
        g_binoff[base + i] = excl;
        excl += c;
    }
}

// ---------------- K3: scatter into sorted order ----------------
__global__ void scatter_kernel() {
    const int cell = blockIdx.x * 256 + threadIdx.x;
    if (cell >= N_CELLS) return;
    const int pos = atomicAdd(&g_binoff[(int)g_key[cell]], 1);
    g_perm[pos] = cell;
}

// ---------------- K4: main — 16 spatially-sorted cells per block ----------------
// 256 threads; thread t handles float4 lane t of each cell (fully coalesced).
// Consecutive sorted cells share corner pixels at IDENTICAL addresses -> L1
// hits, cutting L2 read traffic ~2.5-3x. Unroll x2: 8 loads in flight/thread.
__global__ __launch_bounds__(256)
void roi_pool_kernel(const float* __restrict__ img, float* __restrict__ out) {
    const int t     = threadIdx.x;
    const int slot0 = blockIdx.x * CPB;
    const float4* __restrict__ base = (const float4*)img;

    for (int i = 0; i < CPB; i += 2) {
        const int    cell0 = g_perm[slot0 + i];
        const int    cell1 = g_perm[slot0 + i + 1];
        const int4   off0  = g_offs[cell0];
        const int4   off1  = g_offs[cell1];
        const float4 wt0   = g_wts[cell0];
        const float4 wt1   = g_wts[cell1];

        const float4 a0 = __ldg(base + off0.x + t);
        const float4 b0 = __ldg(base + off0.y + t);
        const float4 c0 = __ldg(base + off0.z + t);
        const float4 d0 = __ldg(base + off0.w + t);
        const float4 a1 = __ldg(base + off1.x + t);
        const float4 b1 = __ldg(base + off1.y + t);
        const float4 c1 = __ldg(base + off1.z + t);
        const float4 d1 = __ldg(base + off1.w + t);

        float4 r;
        r.x = a0.x * wt0.x + b0.x * wt0.y + c0.x * wt0.z + d0.x * wt0.w;
        r.y = a0.y * wt0.x + b0.y * wt0.y + c0.y * wt0.z + d0.y * wt0.w;
        r.z = a0.z * wt0.x + b0.z * wt0.y + c0.z * wt0.z + d0.z * wt0.w;
        r.w = a0.w * wt0.x + b0.w * wt0.y + c0.w * wt0.z + d0.w * wt0.w;
        __stcs((float4*)out + (size_t)cell0 * F4C + t, r);

        r.x = a1.x * wt1.x + b1.x * wt1.y + c1.x * wt1.z + d1.x * wt1.w;
        r.y = a1.y * wt1.x + b1.y * wt1.y + c1.y * wt1.z + d1.y * wt1.w;
        r.z = a1.z * wt1.x + b1.z * wt1.y + c1.z * wt1.z + d1.z * wt1.w;
        r.w = a1.w * wt1.x + b1.w * wt1.y + c1.w * wt1.z + d1.w * wt1.w;
        __stcs((float4*)out + (size_t)cell1 * F4C + t, r);
    }
}

extern "C" void kernel_launch(void* const* d_in, const int* in_sizes, int n_in,
                              void* d_out, int out_size) {
    const float* img  = (const float*)d_in[0];
    const int*   rois = (const int*)d_in[1];
    float*       out  = (float*)d_out;

    zero_kernel<<<(NBINS + 255) / 256, 256>>>();
    setup_kernel<<<(N_CELLS + 255) / 256, 256>>>(rois);
    scan_kernel<<<1, 256>>>();
    scatter_kernel<<<(N_CELLS + 255) / 256, 256>>>();
    roi_pool_kernel<<<N_CELLS / CPB, 256>>>(img, out);
}

// round 11
// speedup vs baseline: 1.2978x; 1.2978x over previous
#include <cuda_runtime.h>
#include <cstdint>

#define POOL 7
#define NUM_ROIS 512
#define IMG_W 128
#define CH 1024
#define N_CELLS (NUM_ROIS * POOL * POOL)   // 25088
#define F4C 256                            // float4 per pixel vector (1024 ch)
#define NBINS (128 * 128)                  // pixel-index bins
#define CPB 16                             // sorted cells per block (25088/16 = 1568)

__device__ int      g_hist[NBINS];
__device__ int      g_binoff[NBINS];
__device__ int      g_perm[N_CELLS];
__device__ uint16_t g_key[N_CELLS];
__device__ int4     g_offs[N_CELLS];       // corner offsets in float4 units
__device__ float4   g_wts[N_CELLS];        // bilinear weights

// ---------------- K1: per-cell params + key + histogram ----------------
__global__ void setup_kernel(const int* __restrict__ rois) {
    const int cell = blockIdx.x * 256 + threadIdx.x;
    if (cell >= N_CELLS) return;

    const int roi = cell / (POOL * POOL);
    const int rem = cell - roi * (POOL * POOL);
    const int py  = rem / POOL;
    const int px  = rem - py * POOL;

    const int x = rois[roi * 4 + 0];
    const int y = rois[roi * 4 + 1];
    const int w = rois[roi * 4 + 2];
    const int h = rois[roi * 4 + 3];

    const float hf = (float)h;
    const float wf = (float)w;

    // half-pixel-center source coords, clamped (matches tf.image.resize bilinear)
    float ys = ((float)py + 0.5f) * hf * (1.0f / POOL) - 0.5f;
    float xs = ((float)px + 0.5f) * wf * (1.0f / POOL) - 0.5f;
    ys = fminf(fmaxf(ys, 0.0f), hf - 1.0f);
    xs = fminf(fmaxf(xs, 0.0f), wf - 1.0f);

    const int y0 = (int)floorf(ys);
    const int x0 = (int)floorf(xs);
    const int y1 = min(y0 + 1, h - 1);
    const int x1 = min(x0 + 1, w - 1);
    const float fy = ys - (float)y0;
    const float fx = xs - (float)x0;

    const int ay0 = y + y0, ay1 = y + y1;
    const int ax0 = x + x0, ax1 = x + x1;

    int4 off;
    off.x = (ay0 * IMG_W + ax0) * F4C;
    off.y = (ay0 * IMG_W + ax1) * F4C;
    off.z = (ay1 * IMG_W + ax0) * F4C;
    off.w = (ay1 * IMG_W + ax1) * F4C;
    g_offs[cell] = off;

    float4 wt;
    wt.x = (1.0f - fy) * (1.0f - fx);
    wt.y = (1.0f - fy) * fx;
    wt.z = fy * (1.0f - fx);
    wt.w = fy * fx;
    g_wts[cell] = wt;

    const int key = ay0 * IMG_W + ax0;     // spatial sort key
    g_key[cell] = (uint16_t)key;
    atomicAdd(&g_hist[key], 1);
}

// ---------------- K2: exclusive scan, 1024 threads, shfl-based ----------------
__global__ __launch_bounds__(1024)
void scan_kernel() {
    __shared__ int warp_sums[32];
    const int t    = threadIdx.x;          // 0..1023
    const int base = t * 16;
    const int lane = t & 31;
    const int wid  = t >> 5;

    int local[16];
    int sum = 0;
#pragma unroll
    for (int i = 0; i < 16; i++) { local[i] = g_hist[base + i]; sum += local[i]; }

    // inclusive scan of per-thread sums across 1024 threads
    int v = sum;
#pragma unroll
    for (int d = 1; d < 32; d <<= 1) {
        int n = __shfl_up_sync(0xFFFFFFFFu, v, d);
        if (lane >= d) v += n;
    }
    if (lane == 31) warp_sums[wid] = v;
    __syncthreads();
    if (wid == 0) {
        int wv = warp_sums[lane];
#pragma unroll
        for (int d = 1; d < 32; d <<= 1) {
            int n = __shfl_up_sync(0xFFFFFFFFu, wv, d);
            if (lane >= d) wv += n;
        }
        warp_sums[lane] = wv;
    }
    __syncthreads();

    int excl = v - sum + (wid > 0 ? warp_sums[wid - 1] : 0);
#pragma unroll
    for (int i = 0; i < 16; i++) { g_binoff[base + i] = excl; excl += local[i]; }
}

// ---------------- K3: scatter into sorted order ----------------
__global__ void scatter_kernel() {
    const int cell = blockIdx.x * 256 + threadIdx.x;
    if (cell >= N_CELLS) return;
    const int pos = atomicAdd(&g_binoff[(int)g_key[cell]], 1);
    g_perm[pos] = cell;
}

// ---------------- K4: main — 16 spatially-sorted cells per block ----------------
// Consecutive sorted cells share corner pixels at IDENTICAL addresses -> L1
// hits, cutting L2 read traffic. Unroll x2: 8 loads in flight per thread.
__global__ __launch_bounds__(256)
void roi_pool_kernel(const float* __restrict__ img, float* __restrict__ out) {
    const int t     = threadIdx.x;
    const int slot0 = blockIdx.x * CPB;
    const float4* __restrict__ base = (const float4*)img;

    for (int i = 0; i < CPB; i += 2) {
        const int    cell0 = g_perm[slot0 + i];
        const int    cell1 = g_perm[slot0 + i + 1];
        const int4   off0  = g_offs[cell0];
        const int4   off1  = g_offs[cell1];
        const float4 wt0   = g_wts[cell0];
        const float4 wt1   = g_wts[cell1];

        const float4 a0 = __ldg(base + off0.x + t);
        const float4 b0 = __ldg(base + off0.y + t);
        const float4 c0 = __ldg(base + off0.z + t);
        const float4 d0 = __ldg(base + off0.w + t);
        const float4 a1 = __ldg(base + off1.x + t);
        const float4 b1 = __ldg(base + off1.y + t);
        const float4 c1 = __ldg(base + off1.z + t);
        const float4 d1 = __ldg(base + off1.w + t);

        float4 r;
        r.x = a0.x * wt0.x + b0.x * wt0.y + c0.x * wt0.z + d0.x * wt0.w;
        r.y = a0.y * wt0.x + b0.y * wt0.y + c0.y * wt0.z + d0.y * wt0.w;
        r.z = a0.z * wt0.x + b0.z * wt0.y + c0.z * wt0.z + d0.z * wt0.w;
        r.w = a0.w * wt0.x + b0.w * wt0.y + c0.w * wt0.z + d0.w * wt0.w;
        __stcs((float4*)out + (size_t)cell0 * F4C + t, r);

        r.x = a1.x * wt1.x + b1.x * wt1.y + c1.x * wt1.z + d1.x * wt1.w;
        r.y = a1.y * wt1.x + b1.y * wt1.y + c1.y * wt1.z + d1.y * wt1.w;
        r.z = a1.z * wt1.x + b1.z * wt1.y + c1.z * wt1.z + d1.z * wt1.w;
        r.w = a1.w * wt1.x + b1.w * wt1.y + c1.w * wt1.z + d1.w * wt1.w;
        __stcs((float4*)out + (size_t)cell1 * F4C + t, r);
    }
}

extern "C" void kernel_launch(void* const* d_in, const int* in_sizes, int n_in,
                              void* d_out, int out_size) {
    const float* img  = (const float*)d_in[0];
    const int*   rois = (const int*)d_in[1];
    float*       out  = (float*)d_out;

    void* hist_ptr = nullptr;
    cudaGetSymbolAddress(&hist_ptr, g_hist);
    cudaMemsetAsync(hist_ptr, 0, NBINS * sizeof(int));

    setup_kernel<<<(N_CELLS + 255) / 256, 256>>>(rois);
    scan_kernel<<<1, 1024>>>();
    scatter_kernel<<<(N_CELLS + 255) / 256, 256>>>();
    roi_pool_kernel<<<N_CELLS / CPB, 256>>>(img, out);
}

// round 13
// speedup vs baseline: 2.1111x; 1.6267x over previous
#include <cuda_runtime.h>
#include <cstdint>

#define POOL 7
#define NUM_ROIS 512
#define IMG_H 128
#define IMG_W 128
#define CH 1024

// 2 cells per 256-thread block: threads 0-127 -> cell0, 128-255 -> cell1.
// Each thread handles float4 indices lane and lane+128 (both warp-coalesced),
// giving 8 outstanding 16B loads per thread with no wavefront inflation.
// A/B vs best (35.0us): plain write-back stores instead of __stcs.
__global__ __launch_bounds__(256, 8)
void roi_pool_kernel(const float* __restrict__ img,
                     const int* __restrict__ rois,
                     float* __restrict__ out) {
    const int half = threadIdx.x >> 7;        // 0 or 1
    const int lane = threadIdx.x & 127;       // 0..127
    const int cell = blockIdx.x * 2 + half;   // roi*49 + py*7 + px

    const int roi  = cell / (POOL * POOL);
    const int rem  = cell - roi * (POOL * POOL);
    const int py   = rem / POOL;
    const int px   = rem - py * POOL;

    const int x = rois[roi * 4 + 0];
    const int y = rois[roi * 4 + 1];
    const int w = rois[roi * 4 + 2];
    const int h = rois[roi * 4 + 3];

    const float hf = (float)h;
    const float wf = (float)w;

    // half-pixel-center source coords, clamped (matches tf.image.resize bilinear)
    float ys = ((float)py + 0.5f) * hf * (1.0f / POOL) - 0.5f;
    float xs = ((float)px + 0.5f) * wf * (1.0f / POOL) - 0.5f;
    ys = fminf(fmaxf(ys, 0.0f), hf - 1.0f);
    xs = fminf(fmaxf(xs, 0.0f), wf - 1.0f);

    const int y0 = (int)floorf(ys);
    const int x0 = (int)floorf(xs);
    const int y1 = min(y0 + 1, h - 1);
    const int x1 = min(x0 + 1, w - 1);
    const float fy = ys - (float)y0;
    const float fx = xs - (float)x0;

    const int ay0 = y + y0, ay1 = y + y1;
    const int ax0 = x + x0, ax1 = x + x1;

    const float4* p00 = (const float4*)(img + ((size_t)(ay0 * IMG_W + ax0)) * CH);
    const float4* p01 = (const float4*)(img + ((size_t)(ay0 * IMG_W + ax1)) * CH);
    const float4* p10 = (const float4*)(img + ((size_t)(ay1 * IMG_W + ax0)) * CH);
    const float4* p11 = (const float4*)(img + ((size_t)(ay1 * IMG_W + ax1)) * CH);

    const float w00 = (1.0f - fy) * (1.0f - fx);
    const float w01 = (1.0f - fy) * fx;
    const float w10 = fy * (1.0f - fx);
    const float w11 = fy * fx;

    const int i0 = lane;          // coalesced: warp covers 512B contiguous
    const int i1 = lane + 128;    // coalesced: warp covers 512B contiguous

    // 8 independent loads in flight before any dependent math
    float4 a0 = __ldg(p00 + i0);
    float4 b0 = __ldg(p01 + i0);
    float4 c0 = __ldg(p10 + i0);
    float4 d0 = __ldg(p11 + i0);
    float4 a1 = __ldg(p00 + i1);
    float4 b1 = __ldg(p01 + i1);
    float4 c1 = __ldg(p10 + i1);
    float4 d1 = __ldg(p11 + i1);

    float4 r0, r1;
    r0.x = a0.x * w00 + b0.x * w01 + c0.x * w10 + d0.x * w11;
    r0.y = a0.y * w00 + b0.y * w01 + c0.y * w10 + d0.y * w11;
    r0.z = a0.z * w00 + b0.z * w01 + c0.z * w10 + d0.z * w11;
    r0.w = a0.w * w00 + b0.w * w01 + c0.w * w10 + d0.w * w11;
    r1.x = a1.x * w00 + b1.x * w01 + c1.x * w10 + d1.x * w11;
    r1.y = a1.y * w00 + b1.y * w01 + c1.y * w10 + d1.y * w11;
    r1.z = a1.z * w00 + b1.z * w01 + c1.z * w10 + d1.z * w11;
    r1.w = a1.w * w00 + b1.w * w01 + c1.w * w10 + d1.w * w11;

    // plain write-back stores: let L2 absorb the output stream and drain lazily
    float4* o = (float4*)(out + (size_t)cell * CH);
    o[i0] = r0;
    o[i1] = r1;
}

extern "C" void kernel_launch(void* const* d_in, const int* in_sizes, int n_in,
                              void* d_out, int out_size) {
    const float* img  = (const float*)d_in[0];
    const int*   rois = (const int*)d_in[1];
    float*       out  = (float*)d_out;

    const int n_cells = NUM_ROIS * POOL * POOL;   // 25088
    roi_pool_kernel<<<n_cells / 2, 256>>>(img, rois, out);
}